// round 9
// baseline (speedup 1.0000x reference)
#include <cuda_runtime.h>
#include <cuda_fp16.h>
#include <cstdint>

#define OUT_DIM 8192
#define IN_DIM  8192
#define NGRP    64                  /* scale groups per output row (GS=128) */
#define O_CTA   32                  /* o-rows per CTA */
#define STAGE_K 256                 /* K elements per stage (1KB per row) */
#define NSTAGES (IN_DIM / STAGE_K)  /* 32 */
#define RING    3
#define ROW_STRIDE 1088             /* 1024 + 64 pad: conflict-free LDS.128 */
#define STAGE_PAD (O_CTA * ROW_STRIDE)      /* 34816 B */
#define STAGE_TX  (O_CTA * 1024)            /* 32768 B per stage */
#define SMEM_BYTES (RING * STAGE_PAD)       /* 104448 B */

// x pre-packed per (kstep, lane): 2 uint4 = fragments for all 4 ntiles.
// k is PERMUTED inside each 16-wide kstep: fragment positions
// (2tig, 2tig+1, 2tig+8, 2tig+9) hold physical k (4tig..4tig+3).
// A reads raw consecutive ints per lane, so the MMA result is unchanged.
__device__ uint4 g_xfrag[512 * 32 * 2];

__global__ void xconv_kernel(const float* __restrict__ x) {
    const int idx  = blockIdx.x * blockDim.x + threadIdx.x;   // 0..16383
    const int lane = idx & 31;
    const int kt   = idx >> 5;
    const int g    = lane >> 2;
    const int tig  = lane & 3;
    const int k0   = kt * 16 + tig * 4;

    unsigned w[8];
    #pragma unroll
    for (int nt = 0; nt < 4; nt++) {
        const int n = nt * 8 + g;
        const float4 a = *reinterpret_cast<const float4*>(x + n * IN_DIM + k0);
        __half2 lo = __floats2half2_rn(a.x, a.y);
        __half2 hi = __floats2half2_rn(a.z, a.w);
        w[nt * 2]     = *reinterpret_cast<unsigned*>(&lo);
        w[nt * 2 + 1] = *reinterpret_cast<unsigned*>(&hi);
    }
    g_xfrag[idx * 2]     = make_uint4(w[0], w[1], w[2], w[3]);
    g_xfrag[idx * 2 + 1] = make_uint4(w[4], w[5], w[6], w[7]);
}

// t in {-1,0,1}: low 16 bits of (t<<14) are exactly fp16(2t). Pack a pair, then
// scale by half2(s/2): products are +-fp16(s), exact (x2 only shifts the exponent).
__device__ __forceinline__ unsigned cvt_pair(unsigned t0, unsigned t1, unsigned sh2) {
    unsigned u0 = t0 << 14;
    unsigned u1 = t1 << 14;
    unsigned p;
    asm("prmt.b32 %0, %1, %2, 0x5410;" : "=r"(p) : "r"(u0), "r"(u1));
    asm("mul.rn.f16x2 %0, %1, %2;" : "=r"(p) : "r"(p), "r"(sh2));
    return p;
}

__device__ __forceinline__ void mma16816(float c[4], unsigned a0, unsigned a1,
                                         unsigned a2, unsigned a3,
                                         unsigned b0, unsigned b1) {
    asm("mma.sync.aligned.m16n8k16.row.col.f32.f16.f16.f32 "
        "{%0,%1,%2,%3}, {%4,%5,%6,%7}, {%8,%9}, {%0,%1,%2,%3};"
        : "+f"(c[0]), "+f"(c[1]), "+f"(c[2]), "+f"(c[3])
        : "r"(a0), "r"(a1), "r"(a2), "r"(a3), "r"(b0), "r"(b1));
}

__device__ __forceinline__ unsigned smem_u32(const void* p) {
    unsigned a;
    asm("{ .reg .u64 t; cvta.to.shared.u64 t, %1; cvt.u32.u64 %0, t; }"
        : "=r"(a) : "l"(p));
    return a;
}
__device__ __forceinline__ void mbar_init(unsigned addr, unsigned cnt) {
    asm volatile("mbarrier.init.shared.b64 [%0], %1;" :: "r"(addr), "r"(cnt) : "memory");
}
__device__ __forceinline__ void mbar_expect_tx(unsigned addr, unsigned bytes) {
    asm volatile("mbarrier.arrive.expect_tx.shared.b64 _, [%0], %1;"
                 :: "r"(addr), "r"(bytes) : "memory");
}
__device__ __forceinline__ void mbar_wait(unsigned addr, unsigned parity) {
    asm volatile(
        "{\n\t.reg .pred P;\n"
        "W%=:\n\t"
        "mbarrier.try_wait.parity.acquire.cta.shared::cta.b64 P, [%0], %1, 0x989680;\n\t"
        "@P bra D%=;\n\t"
        "bra W%=;\n"
        "D%=:\n\t}"
        :: "r"(addr), "r"(parity) : "memory");
}
// 1D bulk copy gmem -> smem, completion via mbarrier complete_tx (SASS: UBLKCP).
__device__ __forceinline__ void bulk_g2s(unsigned dst, const void* src,
                                         unsigned bytes, unsigned mbar) {
    asm volatile(
        "cp.async.bulk.shared::cluster.global.mbarrier::complete_tx::bytes "
        "[%0], [%1], %2, [%3];"
        :: "r"(dst), "l"(src), "r"(bytes), "r"(mbar) : "memory");
}

extern "C" __global__ void __launch_bounds__(256, 2)
tmma_kernel(const int* __restrict__ tern,
            const float* __restrict__ scales,
            float* __restrict__ out)
{
    extern __shared__ char sm[];                 // [RING][32 rows][1088 B]
    __shared__ unsigned long long mbar_store[RING];

    const int tid  = threadIdx.x;
    const int lane = tid & 31;
    const int kg   = tid >> 5;                   // warp 0..7: ksteps 2kg,2kg+1 per stage
    const int g    = lane >> 2;
    const int tig  = lane & 3;
    const int o_tile = blockIdx.x * O_CTA;

    const unsigned ring_b = smem_u32(sm);
    unsigned full_b[RING];
    #pragma unroll
    for (int p = 0; p < RING; p++) full_b[p] = smem_u32(&mbar_store[p]);

    if (tid == 0) {
        #pragma unroll
        for (int p = 0; p < RING; p++) mbar_init(full_b[p], 1);
    }
    __syncthreads();

    // Prologue: fill the ring (stages 0..RING-1), phase 0 of each barrier.
    if (tid == 0) {
        #pragma unroll
        for (int j = 0; j < RING; j++) {
            mbar_expect_tx(full_b[j], STAGE_TX);
            for (int r = 0; r < O_CTA; r++)
                bulk_g2s(ring_b + j * STAGE_PAD + r * ROW_STRIDE,
                         tern + (long)(o_tile + r) * IN_DIM + j * STAGE_K,
                         1024, full_b[j]);
        }
    }

    float acc[2][4][4];
    #pragma unroll
    for (int m = 0; m < 2; m++)
        #pragma unroll
        for (int n = 0; n < 4; n++)
            #pragma unroll
            for (int i = 0; i < 4; i++) acc[m][n][i] = 0.f;

    // B stage-level prefetch (L2-resident xfrag).
    uint4 bcur[2][2], bnxt[2][2];
    {
        const int kglob = 2 * kg;                // stage 0
        #pragma unroll
        for (int j = 0; j < 2; j++) {
            bcur[j][0] = g_xfrag[((kglob + j) * 32 + lane) * 2];
            bcur[j][1] = g_xfrag[((kglob + j) * 32 + lane) * 2 + 1];
        }
    }

    for (int i = 0; i < NSTAGES; i++) {
        const int slot = i % RING;

        // Prefetch next stage's B while waiting on the bulk copies.
        if (i + 1 < NSTAGES) {
            const int kglob = (i + 1) * 16 + 2 * kg;
            #pragma unroll
            for (int j = 0; j < 2; j++) {
                bnxt[j][0] = g_xfrag[((kglob + j) * 32 + lane) * 2];
                bnxt[j][1] = g_xfrag[((kglob + j) * 32 + lane) * 2 + 1];
            }
        }

        mbar_wait(full_b[slot], (i / RING) & 1);

        // Per-stage scales: group = 2*i + (kg>=4) (both ksteps in the same group).
        const int grp = 2 * i + (kg >> 2);
        unsigned sh[4];
        #pragma unroll
        for (int s = 0; s < 4; s++) {
            const float sc = __ldg(scales + (o_tile + s * 8 + g) * NGRP + grp) * 0.5f;
            const __half2 p = __half2half2(__float2half_rn(sc));
            sh[s] = *reinterpret_cast<const unsigned*>(&p);
        }

        // Consume 2 ksteps: lane-conflict-free LDS.128 from the padded tile.
        #pragma unroll
        for (int j = 0; j < 2; j++) {
            const int koff = (2 * kg + j) * 64 + tig * 16;
            #pragma unroll
            for (int m = 0; m < 2; m++) {
                const int4 v0 = *reinterpret_cast<const int4*>(
                    sm + slot * STAGE_PAD + (m * 16 + g) * ROW_STRIDE + koff);
                const int4 v1 = *reinterpret_cast<const int4*>(
                    sm + slot * STAGE_PAD + (m * 16 + 8 + g) * ROW_STRIDE + koff);
                const unsigned a0 = cvt_pair((unsigned)v0.x, (unsigned)v0.y, sh[m * 2]);
                const unsigned a2 = cvt_pair((unsigned)v0.z, (unsigned)v0.w, sh[m * 2]);
                const unsigned a1 = cvt_pair((unsigned)v1.x, (unsigned)v1.y, sh[m * 2 + 1]);
                const unsigned a3 = cvt_pair((unsigned)v1.z, (unsigned)v1.w, sh[m * 2 + 1]);
                mma16816(acc[m][0], a0, a1, a2, a3, bcur[j][0].x, bcur[j][0].y);
                mma16816(acc[m][1], a0, a1, a2, a3, bcur[j][0].z, bcur[j][0].w);
                mma16816(acc[m][2], a0, a1, a2, a3, bcur[j][1].x, bcur[j][1].y);
                mma16816(acc[m][3], a0, a1, a2, a3, bcur[j][1].z, bcur[j][1].w);
            }
        }

        // Every thread is done reading slot i%RING after this barrier; tid 0 may
        // now safely refill it with stage i+RING (consumed at parity (i/RING+1)&1).
        __syncthreads();
        const int jp = i + RING;
        if (jp < NSTAGES && tid == 0) {
            mbar_expect_tx(full_b[slot], STAGE_TX);
            for (int r = 0; r < O_CTA; r++)
                bulk_g2s(ring_b + slot * STAGE_PAD + r * ROW_STRIDE,
                         tern + (long)(o_tile + r) * IN_DIM + jp * STAGE_K,
                         1024, full_b[slot]);
        }

        #pragma unroll
        for (int j = 0; j < 2; j++) {
            bcur[j][0] = bnxt[j][0];
            bcur[j][1] = bnxt[j][1];
        }
    }

    // Deterministic cross-warp K reduction; ring smem reused as the buffer
    // (all stages consumed, no bulk copies outstanding).
    __syncthreads();
    float* red = reinterpret_cast<float*>(sm);   // [8 warps][32 lanes][32 vals]
    #pragma unroll
    for (int m = 0; m < 2; m++)
        #pragma unroll
        for (int nt = 0; nt < 4; nt++)
            #pragma unroll
            for (int i = 0; i < 4; i++)
                red[(kg * 32 + lane) * 32 + m * 16 + nt * 4 + i] = acc[m][nt][i];
    __syncthreads();

    #pragma unroll
    for (int jj = 0; jj < 4; jj++) {
        const int j = kg * 4 + jj;
        float s = red[lane * 32 + j];            // warp 0 partial first
        #pragma unroll
        for (int w = 1; w < 8; w++)
            s += red[(w * 32 + lane) * 32 + j];
        const int m  = j >> 4;
        const int nt = (j >> 2) & 3;
        const int i  = j & 3;
        const int row = o_tile + m * 16 + ((i & 2) ? 8 : 0) + g;
        const int t   = nt * 8 + tig * 2 + (i & 1);
        out[(long)t * OUT_DIM + row] = s;
    }
}

extern "C" void kernel_launch(void* const* d_in, const int* in_sizes, int n_in,
                              void* d_out, int out_size) {
    const float* x      = (const float*)d_in[0];
    const int*   tern   = (const int*)d_in[1];
    const float* scales = (const float*)d_in[2];
    float*       out    = (float*)d_out;

    cudaFuncSetAttribute(tmma_kernel,
                         cudaFuncAttributeMaxDynamicSharedMemorySize, SMEM_BYTES);
    xconv_kernel<<<64, 256>>>(x);
    tmma_kernel<<<OUT_DIM / O_CTA, 256, SMEM_BYTES>>>(tern, scales, out);
}

// round 10
// speedup vs baseline: 1.2496x; 1.2496x over previous
#include <cuda_runtime.h>
#include <cuda_fp16.h>
#include <cstdint>

#define OUT_DIM 8192
#define IN_DIM  8192
#define NGRP    64                  /* scale groups per output row (GS=128) */
#define O_CTA   32                  /* o-rows per CTA */
#define STAGE_K 128                 /* K elements per stage = one scale group (512B/row) */
#define NSTAGES (IN_DIM / STAGE_K)  /* 64 */
#define RING    5
#define ROW_STRIDE 576              /* 512 + 64: ≡64 mod 128 -> conflict-free LDS.128 */
#define STAGE_PAD (O_CTA * ROW_STRIDE)      /* 18432 B */
#define ROW_TX    512
#define WARP_TX   (4 * ROW_TX)              /* 2048 B per producer lane */
#define SMEM_BYTES (RING * STAGE_PAD)       /* 92160 B */

// x pre-packed per (kstep, lane): 2 uint4 = fragments for all 4 ntiles.
// k is PERMUTED inside each 16-wide kstep: fragment positions
// (2tig, 2tig+1, 2tig+8, 2tig+9) hold physical k (4tig..4tig+3).
// A reads raw consecutive ints per lane, so the MMA result is unchanged.
__device__ uint4 g_xfrag[512 * 32 * 2];

__global__ void xconv_kernel(const float* __restrict__ x) {
    const int idx  = blockIdx.x * blockDim.x + threadIdx.x;   // 0..16383
    const int lane = idx & 31;
    const int kt   = idx >> 5;
    const int g    = lane >> 2;
    const int tig  = lane & 3;
    const int k0   = kt * 16 + tig * 4;

    unsigned w[8];
    #pragma unroll
    for (int nt = 0; nt < 4; nt++) {
        const int n = nt * 8 + g;
        const float4 a = *reinterpret_cast<const float4*>(x + n * IN_DIM + k0);
        __half2 lo = __floats2half2_rn(a.x, a.y);
        __half2 hi = __floats2half2_rn(a.z, a.w);
        w[nt * 2]     = *reinterpret_cast<unsigned*>(&lo);
        w[nt * 2 + 1] = *reinterpret_cast<unsigned*>(&hi);
    }
    g_xfrag[idx * 2]     = make_uint4(w[0], w[1], w[2], w[3]);
    g_xfrag[idx * 2 + 1] = make_uint4(w[4], w[5], w[6], w[7]);
}

// t in {-1,0,1}: low 16 bits of (t<<14) are exactly fp16(2t). Pack a pair, then
// scale by half2(s/2): products are +-fp16(s), exact (x2 only shifts the exponent).
__device__ __forceinline__ unsigned cvt_pair(unsigned t0, unsigned t1, unsigned sh2) {
    unsigned u0 = t0 << 14;
    unsigned u1 = t1 << 14;
    unsigned p;
    asm("prmt.b32 %0, %1, %2, 0x5410;" : "=r"(p) : "r"(u0), "r"(u1));
    asm("mul.rn.f16x2 %0, %1, %2;" : "=r"(p) : "r"(p), "r"(sh2));
    return p;
}

__device__ __forceinline__ void mma16816(float c[4], unsigned a0, unsigned a1,
                                         unsigned a2, unsigned a3,
                                         unsigned b0, unsigned b1) {
    asm("mma.sync.aligned.m16n8k16.row.col.f32.f16.f16.f32 "
        "{%0,%1,%2,%3}, {%4,%5,%6,%7}, {%8,%9}, {%0,%1,%2,%3};"
        : "+f"(c[0]), "+f"(c[1]), "+f"(c[2]), "+f"(c[3])
        : "r"(a0), "r"(a1), "r"(a2), "r"(a3), "r"(b0), "r"(b1));
}

__device__ __forceinline__ unsigned smem_u32(const void* p) {
    unsigned a;
    asm("{ .reg .u64 t; cvta.to.shared.u64 t, %1; cvt.u32.u64 %0, t; }"
        : "=r"(a) : "l"(p));
    return a;
}
__device__ __forceinline__ void mbar_init(unsigned addr, unsigned cnt) {
    asm volatile("mbarrier.init.shared.b64 [%0], %1;" :: "r"(addr), "r"(cnt) : "memory");
}
__device__ __forceinline__ void mbar_arrive_expect_tx(unsigned addr, unsigned bytes) {
    asm volatile("mbarrier.arrive.expect_tx.shared.b64 _, [%0], %1;"
                 :: "r"(addr), "r"(bytes) : "memory");
}
__device__ __forceinline__ void mbar_wait(unsigned addr, unsigned parity) {
    asm volatile(
        "{\n\t.reg .pred P;\n"
        "W%=:\n\t"
        "mbarrier.try_wait.parity.acquire.cta.shared::cta.b64 P, [%0], %1, 0x989680;\n\t"
        "@P bra D%=;\n\t"
        "bra W%=;\n"
        "D%=:\n\t}"
        :: "r"(addr), "r"(parity) : "memory");
}
// 1D bulk copy gmem -> smem, completion via mbarrier complete_tx (SASS: UBLKCP).
__device__ __forceinline__ void bulk_g2s(unsigned dst, const void* src,
                                         unsigned bytes, unsigned mbar) {
    asm volatile(
        "cp.async.bulk.shared::cluster.global.mbarrier::complete_tx::bytes "
        "[%0], [%1], %2, [%3];"
        :: "r"(dst), "l"(src), "r"(bytes), "r"(mbar) : "memory");
}

extern "C" __global__ void __launch_bounds__(256, 2)
tmma_kernel(const int* __restrict__ tern,
            const float* __restrict__ scales,
            float* __restrict__ out)
{
    extern __shared__ char sm[];                 // [RING][32 rows][576 B]
    __shared__ unsigned long long mbar_store[RING];

    const int tid  = threadIdx.x;
    const int lane = tid & 31;
    const int kg   = tid >> 5;                   // warp kg consumes kstep kg of each stage
    const int g    = lane >> 2;
    const int tig  = lane & 3;
    const int o_tile = blockIdx.x * O_CTA;
    const bool producer = (lane == 0);           // 8 producer lanes, 4 rows each

    const unsigned ring_b = smem_u32(sm);
    unsigned full_b[RING];
    #pragma unroll
    for (int p = 0; p < RING; p++) full_b[p] = smem_u32(&mbar_store[p]);

    if (tid == 0) {
        #pragma unroll
        for (int p = 0; p < RING; p++) mbar_init(full_b[p], 8);   // 8 producer arrivals
    }
    __syncthreads();

    // Prologue: distributed fill of stages 0..RING-1 (phase 0 of each barrier).
    if (producer) {
        #pragma unroll
        for (int j = 0; j < RING; j++) {
            mbar_arrive_expect_tx(full_b[j], WARP_TX);
            #pragma unroll
            for (int q = 0; q < 4; q++) {
                const int r = kg * 4 + q;
                bulk_g2s(ring_b + j * STAGE_PAD + r * ROW_STRIDE,
                         tern + (long)(o_tile + r) * IN_DIM + j * STAGE_K,
                         ROW_TX, full_b[j]);
            }
        }
    }

    float acc[2][4][4];
    #pragma unroll
    for (int m = 0; m < 2; m++)
        #pragma unroll
        for (int n = 0; n < 4; n++)
            #pragma unroll
            for (int i = 0; i < 4; i++) acc[m][n][i] = 0.f;

    // B stage-level prefetch (L2-resident xfrag): kstep = i*8 + kg.
    uint4 bcur0 = g_xfrag[(kg * 32 + lane) * 2];
    uint4 bcur1 = g_xfrag[(kg * 32 + lane) * 2 + 1];

    for (int i = 0; i < NSTAGES; i++) {
        const int slot = i % RING;

        // Prefetch next stage's B and this stage's scales while TMA lands.
        uint4 bn0, bn1;
        if (i + 1 < NSTAGES) {
            const int kglob = (i + 1) * 8 + kg;
            bn0 = g_xfrag[(kglob * 32 + lane) * 2];
            bn1 = g_xfrag[(kglob * 32 + lane) * 2 + 1];
        }
        unsigned sh[4];
        #pragma unroll
        for (int s = 0; s < 4; s++) {            // stage == scale group
            const float sc = __ldg(scales + (o_tile + s * 8 + g) * NGRP + i) * 0.5f;
            const __half2 p = __half2half2(__float2half_rn(sc));
            sh[s] = *reinterpret_cast<const unsigned*>(&p);
        }

        mbar_wait(full_b[slot], (i / RING) & 1);

        // Consume 1 kstep (warp kg): conflict-free LDS.128 from the padded tile.
        const int koff = kg * 64 + tig * 16;
        #pragma unroll
        for (int m = 0; m < 2; m++) {
            const int4 v0 = *reinterpret_cast<const int4*>(
                sm + slot * STAGE_PAD + (m * 16 + g) * ROW_STRIDE + koff);
            const int4 v1 = *reinterpret_cast<const int4*>(
                sm + slot * STAGE_PAD + (m * 16 + 8 + g) * ROW_STRIDE + koff);
            const unsigned a0 = cvt_pair((unsigned)v0.x, (unsigned)v0.y, sh[m * 2]);
            const unsigned a2 = cvt_pair((unsigned)v0.z, (unsigned)v0.w, sh[m * 2]);
            const unsigned a1 = cvt_pair((unsigned)v1.x, (unsigned)v1.y, sh[m * 2 + 1]);
            const unsigned a3 = cvt_pair((unsigned)v1.z, (unsigned)v1.w, sh[m * 2 + 1]);
            mma16816(acc[m][0], a0, a1, a2, a3, bcur0.x, bcur0.y);
            mma16816(acc[m][1], a0, a1, a2, a3, bcur0.z, bcur0.w);
            mma16816(acc[m][2], a0, a1, a2, a3, bcur1.x, bcur1.y);
            mma16816(acc[m][3], a0, a1, a2, a3, bcur1.z, bcur1.w);
        }

        // All threads done reading this slot after the barrier; refill it with
        // stage i+RING (its consumer waits the flipped parity). Distributed issue.
        __syncthreads();
        const int jp = i + RING;
        if (jp < NSTAGES && producer) {
            mbar_arrive_expect_tx(full_b[slot], WARP_TX);
            #pragma unroll
            for (int q = 0; q < 4; q++) {
                const int r = kg * 4 + q;
                bulk_g2s(ring_b + slot * STAGE_PAD + r * ROW_STRIDE,
                         tern + (long)(o_tile + r) * IN_DIM + jp * STAGE_K,
                         ROW_TX, full_b[slot]);
            }
        }

        bcur0 = bn0;
        bcur1 = bn1;
    }

    // Deterministic cross-warp K reduction; ring smem reused as the buffer.
    __syncthreads();
    float* red = reinterpret_cast<float*>(sm);   // [8 warps][32 lanes][32 vals]
    #pragma unroll
    for (int m = 0; m < 2; m++)
        #pragma unroll
        for (int nt = 0; nt < 4; nt++)
            #pragma unroll
            for (int i = 0; i < 4; i++)
                red[(kg * 32 + lane) * 32 + m * 16 + nt * 4 + i] = acc[m][nt][i];
    __syncthreads();

    #pragma unroll
    for (int jj = 0; jj < 4; jj++) {
        const int j = kg * 4 + jj;
        float s = red[lane * 32 + j];            // warp 0 partial first
        #pragma unroll
        for (int w = 1; w < 8; w++)
            s += red[(w * 32 + lane) * 32 + j];
        const int m  = j >> 4;
        const int nt = (j >> 2) & 3;
        const int i  = j & 3;
        const int row = o_tile + m * 16 + ((i & 2) ? 8 : 0) + g;
        const int t   = nt * 8 + tig * 2 + (i & 1);
        out[(long)t * OUT_DIM + row] = s;
    }
}

extern "C" void kernel_launch(void* const* d_in, const int* in_sizes, int n_in,
                              void* d_out, int out_size) {
    const float* x      = (const float*)d_in[0];
    const int*   tern   = (const int*)d_in[1];
    const float* scales = (const float*)d_in[2];
    float*       out    = (float*)d_out;

    cudaFuncSetAttribute(tmma_kernel,
                         cudaFuncAttributeMaxDynamicSharedMemorySize, SMEM_BYTES);
    xconv_kernel<<<64, 256>>>(x);
    tmma_kernel<<<OUT_DIM / O_CTA, 256, SMEM_BYTES>>>(tern, scales, out);
}

// round 12
// speedup vs baseline: 1.4905x; 1.1928x over previous
#include <cuda_runtime.h>
#include <cuda_fp16.h>
#include <cstdint>

#define OUT_DIM 8192
#define IN_DIM  8192
#define NGRP    64                  /* scale groups per output row (GS=128) */
#define KSTEPS  512
#define KSPLIT  4                   /* K split across the 4 warps of a CTA */
#define KS_W    (KSTEPS / KSPLIT)   /* 128 ksteps per warp */
#define O_CTA   16                  /* o-rows per CTA (each warp: all 16) */
#define STAGE_KS 8                  /* ksteps per stage: 512B per row */
#define NST     (KS_W / STAGE_KS)   /* 16 stages per warp */
#define RING    3
#define ROW_STRIDE 528              /* 512 + 16 pad -> conflict-free LDS.128 */
#define STAGE_BYTES (O_CTA * ROW_STRIDE)        /* 8448 */
#define WARP_SMEM  (RING * STAGE_BYTES)         /* 25344 */
#define SMEM_BYTES (KSPLIT * WARP_SMEM)         /* 101376 ~ 99KB */
#define DEPTH_B 8

// x pre-packed per (kstep, lane): 2 uint4 = fragments for all 4 ntiles.
// k is PERMUTED inside each 16-wide kstep: fragment positions
// (2tig, 2tig+1, 2tig+8, 2tig+9) hold physical k (4tig..4tig+3).
// A reads raw consecutive ints per lane, so the MMA result is unchanged.
__device__ uint4 g_xfrag[KSTEPS * 32 * 2];

__global__ void xconv_kernel(const float* __restrict__ x) {
    const int idx  = blockIdx.x * blockDim.x + threadIdx.x;   // 0..16383
    const int lane = idx & 31;
    const int kt   = idx >> 5;
    const int g    = lane >> 2;
    const int tig  = lane & 3;
    const int k0   = kt * 16 + tig * 4;

    unsigned w[8];
    #pragma unroll
    for (int nt = 0; nt < 4; nt++) {
        const int n = nt * 8 + g;
        const float4 a = *reinterpret_cast<const float4*>(x + n * IN_DIM + k0);
        __half2 lo = __floats2half2_rn(a.x, a.y);
        __half2 hi = __floats2half2_rn(a.z, a.w);
        w[nt * 2]     = *reinterpret_cast<unsigned*>(&lo);
        w[nt * 2 + 1] = *reinterpret_cast<unsigned*>(&hi);
    }
    g_xfrag[idx * 2]     = make_uint4(w[0], w[1], w[2], w[3]);
    g_xfrag[idx * 2 + 1] = make_uint4(w[4], w[5], w[6], w[7]);
}

// t in {-1,0,1}: low 16 bits of (t<<14) are exactly fp16(2t). Pack a pair, then
// scale by half2(s/2): products are +-fp16(s), exact (x2 only shifts the exponent).
__device__ __forceinline__ unsigned cvt_pair(unsigned t0, unsigned t1, unsigned sh2) {
    unsigned u0 = t0 << 14;
    unsigned u1 = t1 << 14;
    unsigned p;
    asm("prmt.b32 %0, %1, %2, 0x5410;" : "=r"(p) : "r"(u0), "r"(u1));
    asm("mul.rn.f16x2 %0, %1, %2;" : "=r"(p) : "r"(p), "r"(sh2));
    return p;
}

__device__ __forceinline__ void mma16816(float c[4], unsigned a0, unsigned a1,
                                         unsigned a2, unsigned a3,
                                         unsigned b0, unsigned b1) {
    asm("mma.sync.aligned.m16n8k16.row.col.f32.f16.f16.f32 "
        "{%0,%1,%2,%3}, {%4,%5,%6,%7}, {%8,%9}, {%0,%1,%2,%3};"
        : "+f"(c[0]), "+f"(c[1]), "+f"(c[2]), "+f"(c[3])
        : "r"(a0), "r"(a1), "r"(a2), "r"(a3), "r"(b0), "r"(b1));
}

__device__ __forceinline__ unsigned smem_u32(const void* p) {
    unsigned a;
    asm("{ .reg .u64 t; cvta.to.shared.u64 t, %1; cvt.u32.u64 %0, t; }"
        : "=r"(a) : "l"(p));
    return a;
}
#define CP_ASYNC16(dst, src) \
    asm volatile("cp.async.cg.shared.global [%0], [%1], 16;" \
                 :: "r"(dst), "l"(src) : "memory")
#define CP_COMMIT() asm volatile("cp.async.commit_group;" ::: "memory")
#define CP_WAIT(n)  asm volatile("cp.async.wait_group %0;" :: "n"(n) : "memory")

extern "C" __global__ void __launch_bounds__(128, 2)
tmma_kernel(const int* __restrict__ tern,
            const float* __restrict__ scales,
            float* __restrict__ out)
{
    extern __shared__ char sm[];   // [4 warps][RING][16 rows][528 B]

    const int tid  = threadIdx.x;
    const int lane = tid & 31;
    const int kg   = tid >> 5;                   // warp = K quarter (0..3)
    const int g    = lane >> 2;
    const int tig  = lane & 3;
    const int o_tile = blockIdx.x * O_CTA;

    // Warp's K window: elt offset kg*2048. Stage s, row r: 512B contiguous burst,
    // lane covers bytes [lane*16, lane*16+16) of the row's stage segment.
    const char* gsrc = reinterpret_cast<const char*>(
        tern + (long)o_tile * IN_DIM + kg * (KS_W * 16)) + lane * 16;
    const unsigned wbase = smem_u32(sm) + kg * WARP_SMEM;
    const char* wsm = sm + kg * WARP_SMEM;

    const uint4* pB = g_xfrag + (long)(kg * KS_W * 32 + lane) * 2;

    float acc[4][4];
    #pragma unroll
    for (int n = 0; n < 4; n++)
        #pragma unroll
        for (int i = 0; i < 4; i++) acc[n][i] = 0.f;

    uint4 bbuf[DEPTH_B][2];

    // Prologue: fill the A ring (RING stages, one commit group per stage).
    #pragma unroll
    for (int s = 0; s < RING; s++) {
        #pragma unroll
        for (int r = 0; r < O_CTA; r++)
            CP_ASYNC16(wbase + s * STAGE_BYTES + r * ROW_STRIDE + lane * 16,
                       gsrc + (long)r * (IN_DIM * 4) + s * 512);
        CP_COMMIT();
    }
    #pragma unroll
    for (int d = 0; d < DEPTH_B; d++) {
        bbuf[d][0] = pB[d * 64];
        bbuf[d][1] = pB[d * 64 + 1];
    }

    for (int i = 0; i < NST; i++) {
        const int slot = i % RING;
        const char* sb = wsm + slot * STAGE_BYTES;

        CP_WAIT(RING - 1);                        // oldest stage landed
        __syncwarp();                             // cross-lane smem visibility

        // Stage == half a scale group? No: stage covers ksteps 8i..8i+7, all in
        // group kg*16 + i (8 ksteps = 128 K = one group). One scale pair/stage.
        const int grp = kg * 16 + i;
        const float s0 = __ldg(scales + (o_tile + g) * NGRP + grp) * 0.5f;
        const float s1 = __ldg(scales + (o_tile + 8 + g) * NGRP + grp) * 0.5f;
        const __half2 p0 = __half2half2(__float2half_rn(s0));
        const __half2 p1 = __half2half2(__float2half_rn(s1));
        const unsigned sh0 = *reinterpret_cast<const unsigned*>(&p0);
        const unsigned sh1 = *reinterpret_cast<const unsigned*>(&p1);

        #pragma unroll
        for (int j = 0; j < STAGE_KS; j++) {
            const int ksg = i * STAGE_KS + j;     // warp-local kstep index
            const int ib  = ksg & (DEPTH_B - 1);
            const int koff = j * 64 + tig * 16;

            const int4 va0 = *reinterpret_cast<const int4*>(
                sb + g * ROW_STRIDE + koff);                  // row o+g
            const int4 va1 = *reinterpret_cast<const int4*>(
                sb + (8 + g) * ROW_STRIDE + koff);            // row o+8+g
            const uint4 vb0 = bbuf[ib][0];
            const uint4 vb1 = bbuf[ib][1];

            const int kb = ksg + DEPTH_B;
            if (kb < KS_W) {
                bbuf[ib][0] = pB[kb * 64];
                bbuf[ib][1] = pB[kb * 64 + 1];
            }

            const unsigned a0 = cvt_pair((unsigned)va0.x, (unsigned)va0.y, sh0);
            const unsigned a2 = cvt_pair((unsigned)va0.z, (unsigned)va0.w, sh0);
            const unsigned a1 = cvt_pair((unsigned)va1.x, (unsigned)va1.y, sh1);
            const unsigned a3 = cvt_pair((unsigned)va1.z, (unsigned)va1.w, sh1);

            mma16816(acc[0], a0, a1, a2, a3, vb0.x, vb0.y);
            mma16816(acc[1], a0, a1, a2, a3, vb0.z, vb0.w);
            mma16816(acc[2], a0, a1, a2, a3, vb1.x, vb1.y);
            mma16816(acc[3], a0, a1, a2, a3, vb1.z, vb1.w);
        }

        // Refill this slot with stage i+RING (same warp already consumed it;
        // DMA data cannot land before the LDS above completed). Dummy commits
        // at the tail keep wait_group counts uniform.
        __syncwarp();
        const int sp = i + RING;
        if (sp < NST) {
            #pragma unroll
            for (int r = 0; r < O_CTA; r++)
                CP_ASYNC16(wbase + slot * STAGE_BYTES + r * ROW_STRIDE + lane * 16,
                           gsrc + (long)r * (IN_DIM * 4) + sp * 512);
        }
        CP_COMMIT();
    }

    // Deterministic cross-warp K reduction; ring smem reused as the buffer.
    CP_WAIT(0);
    __syncthreads();
    float* red = reinterpret_cast<float*>(sm);   // [KSPLIT][32][16]
    #pragma unroll
    for (int nt = 0; nt < 4; nt++)
        #pragma unroll
        for (int i = 0; i < 4; i++)
            red[(kg * 32 + lane) * 16 + nt * 4 + i] = acc[nt][i];
    __syncthreads();

    if (kg == 0) {
        #pragma unroll
        for (int nt = 0; nt < 4; nt++) {
            const int t = nt * 8 + tig * 2;
            #pragma unroll
            for (int i = 0; i < 4; i++) {
                const int idx = nt * 4 + i;
                float s = red[lane * 16 + idx];
                #pragma unroll
                for (int w = 1; w < KSPLIT; w++)
                    s += red[(w * 32 + lane) * 16 + idx];
                const int row = o_tile + ((i & 2) ? 8 : 0) + g;
                const int tt  = t + (i & 1);
                out[(long)tt * OUT_DIM + row] = s;
            }
        }
    }
}

extern "C" void kernel_launch(void* const* d_in, const int* in_sizes, int n_in,
                              void* d_out, int out_size) {
    const float* x      = (const float*)d_in[0];
    const int*   tern   = (const int*)d_in[1];
    const float* scales = (const float*)d_in[2];
    float*       out    = (float*)d_out;

    cudaFuncSetAttribute(tmma_kernel,
                         cudaFuncAttributeMaxDynamicSharedMemorySize, SMEM_BYTES);
    xconv_kernel<<<64, 256>>>(x);
    tmma_kernel<<<OUT_DIM / O_CTA, 128, SMEM_BYTES>>>(tern, scales, out);
}